// round 4
// baseline (speedup 1.0000x reference)
#include <cuda_runtime.h>
#include <cstdint>

typedef unsigned long long ull;

#define MAXN (1 << 21)

// g_nodes[i] packs {p : lo 32, partial-sum : hi 32}. One 8B word => each chase
// hop is a single L2 access. After a node is final: p == N, hi = full path sum.
__device__ ull   g_nodes[MAXN];
__device__ float g_val[MAXN];

__device__ __forceinline__ ull pack_node(unsigned p, float t) {
    return ((ull)__float_as_uint(t) << 32) | (ull)p;
}
__device__ __forceinline__ ull ld_cg(const ull* a) {
    ull v;
    asm volatile("ld.relaxed.gpu.b64 %0, [%1];" : "=l"(v) : "l"(a) : "memory");
    return v;
}
__device__ __forceinline__ void st_cg(ull* a, ull v) {
    asm volatile("st.relaxed.gpu.b64 [%0], %1;" :: "l"(a), "l"(v) : "memory");
}

// ---------------------------------------------------------------------------
// Phase 1: feature transform + linear + sigmoid -> term; publish (parent,term)
// for every node. Kernel boundary = readiness barrier for the resolve phase.
// ---------------------------------------------------------------------------
__global__ __launch_bounds__(256)
void phase1_kernel(const float* __restrict__ diff,
                   const float* __restrict__ attr,
                   const float* __restrict__ weight,
                   const float* __restrict__ bias,
                   const int*   __restrict__ parent,
                   int N)
{
    __shared__ float s_attr[256 * 15];
    const int base = blockIdx.x * 256;
    const int tid  = threadIdx.x;
    const int i    = base + tid;

    // Prefetch the per-node scalars so they overlap the float4 stream.
    float d_pref = 0.0f;
    int   p_pref = 0;
    if (i < N) {
        d_pref = __ldcs(diff + i);
        p_pref = __ldcs(parent + i);
    }

    if (base + 256 <= N) {
        const float4* src = (const float4*)(attr + (size_t)base * 15);
        float4* dst = (float4*)s_attr;
        dst[tid]       = __ldcs(src + tid);
        dst[tid + 256] = __ldcs(src + tid + 256);
        dst[tid + 512] = __ldcs(src + tid + 512);
        if (tid < 192) dst[tid + 768] = __ldcs(src + tid + 768);
    } else {
        const int rem = (N - base) * 15;
        for (int k = tid; k < rem; k += 256)
            s_attr[k] = __ldcs(attr + (size_t)base * 15 + k);
    }
    __syncthreads();

    if (i >= N) return;

    const float* f = s_attr + tid * 15;

    float w[17];
    #pragma unroll
    for (int k = 0; k < 17; k++) w[k] = __ldg(weight + k);

    float z = __ldg(bias);
    z += w[0] * f[0] + w[1] * f[1] + w[2] * f[2] + w[3] * f[3] + w[4] * f[4];
    #pragma unroll
    for (int j = 6; j < 15; j++)
        z += w[j - 1] * __logf(fabsf(f[j]) + 1e-10f);
    z += w[14] * (sqrtf(f[7]) / (sqrtf(f[6]) + 1e-10f));
    float sn, cs;
    __sincosf(f[5], &sn, &cs);
    z += w[15] * cs + w[16] * sn;

    const float cc = 1.0f / (1.0f + __expf(-z));
    const float t  = d_pref * cc;

    const unsigned p = (p_pref < 0) ? (unsigned)N : (unsigned)p_pref;
    g_nodes[i] = pack_node(p, t);
}

// ---------------------------------------------------------------------------
// Resolve one slab [start, end) with 4 independent chains per thread (ILP-4).
// Chains are strided (i, i+T, i+2T, i+3T over the slab) so the initial 8B
// loads stay coalesced, and the 4 dependent-load chains interleave to hide
// L2 latency 4x. Invariant: all nodes < start are final (p == N). Concurrent
// in-slab compression races are benign (every published 8B word is a valid
// (ancestor, partial-sum) state; p strictly decreases).
// ---------------------------------------------------------------------------
__global__ __launch_bounds__(256)
void resolve_slab_kernel(int start, int end, int N)
{
    const int T   = gridDim.x * blockDim.x;          // threads = ceil(size/4)
    const int t   = blockIdx.x * blockDim.x + threadIdx.x;
    const unsigned Nu = (unsigned)N;

    int      idx[4];
    unsigned p[4];
    float    s[4];

    #pragma unroll
    for (int k = 0; k < 4; k++) {
        const int i = start + t + k * T;
        idx[k] = i;
        if (i < end) {
            const ull cur = ld_cg(&g_nodes[i]);
            p[k] = (unsigned)cur;
            s[k] = __uint_as_float((unsigned)(cur >> 32));
        } else {
            p[k] = Nu;
            s[k] = 0.0f;
        }
    }

    for (;;) {
        bool any = false;
        #pragma unroll
        for (int k = 0; k < 4; k++) {
            if (p[k] != Nu) {
                any = true;
                const ull m = ld_cg(&g_nodes[p[k]]);
                s[k] += __uint_as_float((unsigned)(m >> 32));
                p[k] = (unsigned)m;
                st_cg(&g_nodes[idx[k]], pack_node(p[k], s[k]));
            }
        }
        if (!any) break;
    }

    #pragma unroll
    for (int k = 0; k < 4; k++)
        if (idx[k] < end) g_val[idx[k]] = s[k];
}

// ---------------------------------------------------------------------------
// Gather: out[j] = g_val[pn[j]]. Streaming hints on the 128MB pixel traffic
// keep the 8MB g_val hot in L2; 8 pixels/thread.
// ---------------------------------------------------------------------------
__global__ __launch_bounds__(256)
void gather_kernel(const int* __restrict__ pn, float* __restrict__ out, int M)
{
    const int j  = blockIdx.x * blockDim.x + threadIdx.x;
    const int i8 = j * 8;
    if (i8 + 7 < M) {
        const int4 pa = __ldcs((const int4*)pn + 2 * j);
        const int4 pb = __ldcs((const int4*)pn + 2 * j + 1);
        float4 oa, ob;
        oa.x = __ldg(&g_val[pa.x]);
        oa.y = __ldg(&g_val[pa.y]);
        oa.z = __ldg(&g_val[pa.z]);
        oa.w = __ldg(&g_val[pa.w]);
        ob.x = __ldg(&g_val[pb.x]);
        ob.y = __ldg(&g_val[pb.y]);
        ob.z = __ldg(&g_val[pb.z]);
        ob.w = __ldg(&g_val[pb.w]);
        __stcs((float4*)out + 2 * j, oa);
        __stcs((float4*)out + 2 * j + 1, ob);
    } else {
        for (int k = i8; k < M; k++)
            out[k] = __ldg(&g_val[__ldcs(pn + k)]);
    }
}

extern "C" void kernel_launch(void* const* d_in, const int* in_sizes, int n_in,
                              void* d_out, int out_size)
{
    const float* diff   = (const float*)d_in[0];
    const float* attr   = (const float*)d_in[1];
    const float* weight = (const float*)d_in[2];
    const float* bias   = (const float*)d_in[3];
    const int*   parent = (const int*)d_in[4];
    const int*   pn     = (const int*)d_in[5];
    float*       out    = (float*)d_out;

    const int N = in_sizes[0];
    const int M = out_size;

    phase1_kernel<<<(N + 255) / 256, 256>>>(diff, attr, weight, bias, parent, N);

    // Geometric slabs: [0,8K), [8K,32K), [32K,128K), [128K,512K), [512K,N).
    int bounds[6];
    bounds[0] = 0;
    int b = N >> 8;
    for (int k = 1; k <= 4; k++) { bounds[k] = (b < N) ? b : N; b <<= 2; }
    bounds[5] = N;
    for (int k = 0; k < 5; k++) {
        const int s = bounds[k], e = bounds[k + 1];
        if (e > s) {
            const int threads = (e - s + 3) / 4;
            resolve_slab_kernel<<<(threads + 255) / 256, 256>>>(s, e, N);
        }
    }

    const int gthreads = (M + 7) / 8;
    gather_kernel<<<(gthreads + 255) / 256, 256>>>(pn, out, M);
}

// round 5
// speedup vs baseline: 1.1097x; 1.1097x over previous
#include <cuda_runtime.h>
#include <cstdint>

typedef unsigned long long ull;

#define MAXN (1 << 21)

// g_nodes[i] packs {p : lo 32, partial-sum : hi 32}. One 8B word => each chase
// hop is a single L2 access. Final state: p == N, hi = full path sum.
__device__ ull   g_nodes[MAXN];
__device__ float g_val[MAXN];

__device__ __forceinline__ ull pack_node(unsigned p, float t) {
    return ((ull)__float_as_uint(t) << 32) | (ull)p;
}
__device__ __forceinline__ ull ld_cg(const ull* a) {
    ull v;
    asm volatile("ld.relaxed.gpu.b64 %0, [%1];" : "=l"(v) : "l"(a) : "memory");
    return v;
}
__device__ __forceinline__ void st_cg(ull* a, ull v) {
    asm volatile("st.relaxed.gpu.b64 [%0], %1;" :: "l"(a), "l"(v) : "memory");
}

__device__ __forceinline__ float node_score(const float* f, const float* w, float b)
{
    float z = b;
    z += w[0] * f[0] + w[1] * f[1] + w[2] * f[2] + w[3] * f[3] + w[4] * f[4];
    #pragma unroll
    for (int j = 6; j < 15; j++)
        z += w[j - 1] * __logf(fabsf(f[j]) + 1e-10f);
    z += w[14] * (sqrtf(f[7]) / (sqrtf(f[6]) + 1e-10f));
    float sn, cs;
    __sincosf(f[5], &sn, &cs);
    z += w[15] * cs + w[16] * sn;
    return 1.0f / (1.0f + __expf(-z));
}

// ---------------------------------------------------------------------------
// Phase 1: 512 nodes per 256-thread block (2 nodes/thread) to double the
// number of front-batched float4 loads in flight (MLP). Computes
// term = diff * sigmoid(linear(rescale(attr))) and publishes (parent, term).
// ---------------------------------------------------------------------------
__global__ __launch_bounds__(256)
void phase1_kernel(const float* __restrict__ diff,
                   const float* __restrict__ attr,
                   const float* __restrict__ weight,
                   const float* __restrict__ bias,
                   const int*   __restrict__ parent,
                   int N)
{
    __shared__ float s_attr[512 * 15];
    const int base = blockIdx.x * 512;
    const int tid  = threadIdx.x;
    const int i0   = base + tid;
    const int i1   = base + tid + 256;

    // Prefetch per-node scalars (overlap with the float4 stream).
    float d0 = 0.0f, d1 = 0.0f;
    int   q0 = 0,    q1 = 0;
    if (i0 < N) { d0 = __ldcs(diff + i0); q0 = __ldcs(parent + i0); }
    if (i1 < N) { d1 = __ldcs(diff + i1); q1 = __ldcs(parent + i1); }

    if (base + 512 <= N) {
        const float4* src = (const float4*)(attr + (size_t)base * 15);
        float4* dst = (float4*)s_attr;
        // 512*15/4 = 1920 float4s per block
        #pragma unroll
        for (int k = 0; k < 7; k++)
            dst[tid + k * 256] = __ldcs(src + tid + k * 256);
        if (tid < 128) dst[tid + 1792] = __ldcs(src + tid + 1792);
    } else {
        const int rem = (N - base) * 15;
        for (int k = tid; k < rem; k += 256)
            s_attr[k] = __ldcs(attr + (size_t)base * 15 + k);
    }
    __syncthreads();

    float w[17];
    #pragma unroll
    for (int k = 0; k < 17; k++) w[k] = __ldg(weight + k);
    const float b = __ldg(bias);

    if (i0 < N) {
        const float t = d0 * node_score(s_attr + tid * 15, w, b);
        const unsigned p = (q0 < 0) ? (unsigned)N : (unsigned)q0;
        g_nodes[i0] = pack_node(p, t);
    }
    if (i1 < N) {
        const float t = d1 * node_score(s_attr + (tid + 256) * 15, w, b);
        const unsigned p = (q1 < 0) ? (unsigned)N : (unsigned)q1;
        g_nodes[i1] = pack_node(p, t);
    }
}

// ---------------------------------------------------------------------------
// Resolve one slab [start, end), 1 thread per node. Invariant: nodes < start
// are final (p == N). parent[i] < i => with ratio-8 slabs a chase needs ~2
// in-slab hops before reading a final ancestor. Concurrent compression races
// are benign: every published 8B word is a valid (ancestor, partial-sum)
// state, and p strictly decreases.
// ---------------------------------------------------------------------------
__global__ __launch_bounds__(256)
void resolve_slab_kernel(int start, int end, int N)
{
    const int i = start + blockIdx.x * blockDim.x + threadIdx.x;
    if (i >= end) return;
    const unsigned Nu = (unsigned)N;

    ull cur = ld_cg(&g_nodes[i]);
    unsigned p = (unsigned)cur;
    float    t = __uint_as_float((unsigned)(cur >> 32));

    while (p != Nu) {
        const ull m = ld_cg(&g_nodes[p]);
        t += __uint_as_float((unsigned)(m >> 32));
        p = (unsigned)m;
        st_cg(&g_nodes[i], pack_node(p, t));
    }
    g_val[i] = t;
}

// ---------------------------------------------------------------------------
// Gather: out[j] = g_val[pn[j]]. Streaming hints on the 128MB pixel traffic
// keep the 8MB g_val hot in L2; 8 pixels/thread. LTS-sector-bound.
// ---------------------------------------------------------------------------
__global__ __launch_bounds__(256)
void gather_kernel(const int* __restrict__ pn, float* __restrict__ out, int M)
{
    const int j  = blockIdx.x * blockDim.x + threadIdx.x;
    const int i8 = j * 8;
    if (i8 + 7 < M) {
        const int4 pa = __ldcs((const int4*)pn + 2 * j);
        const int4 pb = __ldcs((const int4*)pn + 2 * j + 1);
        float4 oa, ob;
        oa.x = __ldg(&g_val[pa.x]);
        oa.y = __ldg(&g_val[pa.y]);
        oa.z = __ldg(&g_val[pa.z]);
        oa.w = __ldg(&g_val[pa.w]);
        ob.x = __ldg(&g_val[pb.x]);
        ob.y = __ldg(&g_val[pb.y]);
        ob.z = __ldg(&g_val[pb.z]);
        ob.w = __ldg(&g_val[pb.w]);
        __stcs((float4*)out + 2 * j, oa);
        __stcs((float4*)out + 2 * j + 1, ob);
    } else {
        for (int k = i8; k < M; k++)
            out[k] = __ldg(&g_val[__ldcs(pn + k)]);
    }
}

extern "C" void kernel_launch(void* const* d_in, const int* in_sizes, int n_in,
                              void* d_out, int out_size)
{
    const float* diff   = (const float*)d_in[0];
    const float* attr   = (const float*)d_in[1];
    const float* weight = (const float*)d_in[2];
    const float* bias   = (const float*)d_in[3];
    const int*   parent = (const int*)d_in[4];
    const int*   pn     = (const int*)d_in[5];
    float*       out    = (float*)d_out;

    const int N = in_sizes[0];
    const int M = out_size;

    phase1_kernel<<<(N + 511) / 512, 256>>>(diff, attr, weight, bias, parent, N);

    // 3 slabs: [0, N/64), [N/64, N/8), [N/8, N)  ->  [0,32K),[32K,256K),[256K,2M)
    int bounds[4];
    bounds[0] = 0;
    bounds[1] = (N >> 6) > 0 ? (N >> 6) : N;
    bounds[2] = (N >> 3) > bounds[1] ? (N >> 3) : N;
    bounds[3] = N;
    for (int k = 0; k < 3; k++) {
        const int s = bounds[k], e = bounds[k + 1];
        if (e > s)
            resolve_slab_kernel<<<(e - s + 255) / 256, 256>>>(s, e, N);
    }

    const int gthreads = (M + 7) / 8;
    gather_kernel<<<(gthreads + 255) / 256, 256>>>(pn, out, M);
}

// round 6
// speedup vs baseline: 1.1105x; 1.0007x over previous
#include <cuda_runtime.h>
#include <cstdint>

typedef unsigned long long ull;

#define MAXN (1 << 21)

// g_nodes[i] packs {p : lo 32, sum : hi 32} in one 8B word. After a node's
// slab resolves: p == N and hi = full path sum. Gather reads the hi word.
__device__ ull g_nodes[MAXN];

__device__ __forceinline__ ull pack_node(unsigned p, float t) {
    return ((ull)__float_as_uint(t) << 32) | (ull)p;
}
__device__ __forceinline__ void st_cg(ull* a, ull v) {
    asm volatile("st.relaxed.gpu.b64 [%0], %1;" :: "l"(a), "l"(v) : "memory");
}

__device__ __forceinline__ float node_score(const float* f, const float* w, float b)
{
    float z = b;
    z += w[0] * f[0] + w[1] * f[1] + w[2] * f[2] + w[3] * f[3] + w[4] * f[4];
    #pragma unroll
    for (int j = 6; j < 15; j++)
        z += w[j - 1] * __logf(fabsf(f[j]) + 1e-10f);
    z += w[14] * (sqrtf(f[7]) / (sqrtf(f[6]) + 1e-10f));
    float sn, cs;
    __sincosf(f[5], &sn, &cs);
    z += w[15] * cs + w[16] * sn;
    return 1.0f / (1.0f + __expf(-z));
}

// ---------------------------------------------------------------------------
// Phase 1: 512 nodes per 256-thread block. term = diff * sigmoid(linear(
// rescale(attr))); publish (parent, term) per node. Kernel boundary =
// readiness barrier (plus per-launch L1 flush) for the resolve phase.
// ---------------------------------------------------------------------------
__global__ __launch_bounds__(256)
void phase1_kernel(const float* __restrict__ diff,
                   const float* __restrict__ attr,
                   const float* __restrict__ weight,
                   const float* __restrict__ bias,
                   const int*   __restrict__ parent,
                   int N)
{
    __shared__ float s_attr[512 * 15];
    const int base = blockIdx.x * 512;
    const int tid  = threadIdx.x;
    const int i0   = base + tid;
    const int i1   = base + tid + 256;

    float d0 = 0.0f, d1 = 0.0f;
    int   q0 = 0,    q1 = 0;
    if (i0 < N) { d0 = __ldcs(diff + i0); q0 = __ldcs(parent + i0); }
    if (i1 < N) { d1 = __ldcs(diff + i1); q1 = __ldcs(parent + i1); }

    if (base + 512 <= N) {
        const float4* src = (const float4*)(attr + (size_t)base * 15);
        float4* dst = (float4*)s_attr;
        #pragma unroll
        for (int k = 0; k < 7; k++)
            dst[tid + k * 256] = __ldcs(src + tid + k * 256);
        if (tid < 128) dst[tid + 1792] = __ldcs(src + tid + 1792);
    } else {
        const int rem = (N - base) * 15;
        for (int k = tid; k < rem; k += 256)
            s_attr[k] = __ldcs(attr + (size_t)base * 15 + k);
    }
    __syncthreads();

    float w[17];
    #pragma unroll
    for (int k = 0; k < 17; k++) w[k] = __ldg(weight + k);
    const float b = __ldg(bias);

    if (i0 < N) {
        const float t = d0 * node_score(s_attr + tid * 15, w, b);
        g_nodes[i0] = pack_node((q0 < 0) ? (unsigned)N : (unsigned)q0, t);
    }
    if (i1 < N) {
        const float t = d1 * node_score(s_attr + (tid + 256) * 15, w, b);
        g_nodes[i1] = pack_node((q1 < 0) ? (unsigned)N : (unsigned)q1, t);
    }
}

// ---------------------------------------------------------------------------
// Resolve slab [start, end), 1 thread/node, read-only chase, single final
// publish. Stale L1 reads of in-slab nodes return the original (parent,term)
// state, which is still valid; p strictly decreases -> always terminates.
// Prior-slab finals are fresh (L1 flushed at launch).
// ---------------------------------------------------------------------------
__global__ __launch_bounds__(256)
void resolve_slab_kernel(int start, int end, int N)
{
    const int i = start + blockIdx.x * blockDim.x + threadIdx.x;
    if (i >= end) return;
    const unsigned Nu = (unsigned)N;

    ull cur = __ldg(&g_nodes[i]);
    unsigned p = (unsigned)cur;
    float    t = __uint_as_float((unsigned)(cur >> 32));

    while (p != Nu) {
        const ull m = __ldg(&g_nodes[p]);
        t += __uint_as_float((unsigned)(m >> 32));
        p = (unsigned)m;
    }
    st_cg(&g_nodes[i], pack_node(Nu, t));
}

// ---------------------------------------------------------------------------
// Resolve slab with 2 interleaved independent chains per thread (ILP-2) for
// the big final slab: doubles outstanding dependent loads at unchanged
// occupancy (grid stays in the thousands of blocks).
// ---------------------------------------------------------------------------
__global__ __launch_bounds__(256)
void resolve_slab2_kernel(int start, int end, int N)
{
    const int T = gridDim.x * blockDim.x;
    const int t = blockIdx.x * blockDim.x + threadIdx.x;
    const int ia = start + t;
    const int ib = start + t + T;
    const unsigned Nu = (unsigned)N;

    unsigned pa = Nu, pb = Nu;
    float    sa = 0.f, sb = 0.f;
    if (ia < end) {
        const ull c = __ldg(&g_nodes[ia]);
        pa = (unsigned)c; sa = __uint_as_float((unsigned)(c >> 32));
    }
    if (ib < end) {
        const ull c = __ldg(&g_nodes[ib]);
        pb = (unsigned)c; sb = __uint_as_float((unsigned)(c >> 32));
    }

    while (pa != Nu || pb != Nu) {
        if (pa != Nu) {
            const ull m = __ldg(&g_nodes[pa]);
            sa += __uint_as_float((unsigned)(m >> 32));
            pa = (unsigned)m;
        }
        if (pb != Nu) {
            const ull m = __ldg(&g_nodes[pb]);
            sb += __uint_as_float((unsigned)(m >> 32));
            pb = (unsigned)m;
        }
    }

    if (ia < end) st_cg(&g_nodes[ia], pack_node(Nu, sa));
    if (ib < end) st_cg(&g_nodes[ib], pack_node(Nu, sb));
}

// ---------------------------------------------------------------------------
// Gather: out[j] = hi32(g_nodes[pn[j]]). Streaming hints keep the 128MB pixel
// traffic from evicting the 16MB g_nodes from L2; 8 pixels/thread.
// ---------------------------------------------------------------------------
__global__ __launch_bounds__(256)
void gather_kernel(const int* __restrict__ pn, float* __restrict__ out, int M)
{
    const int j  = blockIdx.x * blockDim.x + threadIdx.x;
    const int i8 = j * 8;
    if (i8 + 7 < M) {
        const int4 pa = __ldcs((const int4*)pn + 2 * j);
        const int4 pb = __ldcs((const int4*)pn + 2 * j + 1);
        float4 oa, ob;
        oa.x = __uint_as_float((unsigned)(__ldg(&g_nodes[pa.x]) >> 32));
        oa.y = __uint_as_float((unsigned)(__ldg(&g_nodes[pa.y]) >> 32));
        oa.z = __uint_as_float((unsigned)(__ldg(&g_nodes[pa.z]) >> 32));
        oa.w = __uint_as_float((unsigned)(__ldg(&g_nodes[pa.w]) >> 32));
        ob.x = __uint_as_float((unsigned)(__ldg(&g_nodes[pb.x]) >> 32));
        ob.y = __uint_as_float((unsigned)(__ldg(&g_nodes[pb.y]) >> 32));
        ob.z = __uint_as_float((unsigned)(__ldg(&g_nodes[pb.z]) >> 32));
        ob.w = __uint_as_float((unsigned)(__ldg(&g_nodes[pb.w]) >> 32));
        __stcs((float4*)out + 2 * j, oa);
        __stcs((float4*)out + 2 * j + 1, ob);
    } else {
        for (int k = i8; k < M; k++)
            out[k] = __uint_as_float((unsigned)(__ldg(&g_nodes[__ldcs(pn + k)]) >> 32));
    }
}

extern "C" void kernel_launch(void* const* d_in, const int* in_sizes, int n_in,
                              void* d_out, int out_size)
{
    const float* diff   = (const float*)d_in[0];
    const float* attr   = (const float*)d_in[1];
    const float* weight = (const float*)d_in[2];
    const float* bias   = (const float*)d_in[3];
    const int*   parent = (const int*)d_in[4];
    const int*   pn     = (const int*)d_in[5];
    float*       out    = (float*)d_out;

    const int N = in_sizes[0];
    const int M = out_size;

    phase1_kernel<<<(N + 511) / 512, 256>>>(diff, attr, weight, bias, parent, N);

    // Slabs: [0, N/64), [N/64, N/8) with 1 thread/node; [N/8, N) with ILP-2.
    const int b1 = (N >> 6) > 0 ? (N >> 6) : N;
    const int b2 = (N >> 3) > b1 ? (N >> 3) : N;
    if (b1 > 0)
        resolve_slab_kernel<<<(b1 + 255) / 256, 256>>>(0, b1, N);
    if (b2 > b1)
        resolve_slab_kernel<<<(b2 - b1 + 255) / 256, 256>>>(b1, b2, N);
    if (N > b2) {
        const int threads = (N - b2 + 1) / 2;
        resolve_slab2_kernel<<<(threads + 255) / 256, 256>>>(b2, N, N);
    }

    const int gthreads = (M + 7) / 8;
    gather_kernel<<<(gthreads + 255) / 256, 256>>>(pn, out, M);
}